// round 15
// baseline (speedup 1.0000x reference)
#include <cuda_runtime.h>
#include <cuda_fp16.h>
#include <math.h>
#include <stdint.h>

#define BATCH 4
#define SEQ   2048
#define HIDN  512
#define NH    8
#define HD    64
#define SWIN  250
#define MTOT  (BATCH*SEQ)            // 8192
#define MATSZ (BATCH*NH*SEQ*HD)      // 4.19M elements per Q/K/V matrix

// ---------------- device-global scratch (fp16, all single-rounded) ----------
__device__ __half g_Xh[MTOT*HIDN];                    // X rounded once
__device__ __half g_Wh[3*HIDN*HIDN];                  // Wq|Wk|Wv rounded once
__device__ __half g_Ah[MTOT*HIDN];                    // attn out, rounded once
__device__ __half g_Woh[HIDN*HIDN];                   // Wo rounded once
__device__ __half g_Qh[MATSZ];                        // RoPE'd Q (UNscaled)
__device__ __half g_Kh[MATSZ];                        // RoPE'd K
__device__ __half g_Vh[MATSZ];                        // V
__device__ float2 g_rope[SEQ*32];                     // cos,sin per (pos, freq)

// ---------------- PTX helpers ----------------------------------------------
__device__ __forceinline__ uint32_t smem_u32(const void* p) {
    uint32_t a;
    asm("{ .reg .u64 t; cvta.to.shared.u64 t, %1; cvt.u32.u64 %0, t; }"
        : "=r"(a) : "l"(p));
    return a;
}
__device__ __forceinline__ void cp16(uint32_t d, const void* s) {
    asm volatile("cp.async.cg.shared.global [%0], [%1], 16;"
                 :: "r"(d), "l"(__cvta_generic_to_global(s)) : "memory");
}
#define CP_COMMIT() asm volatile("cp.async.commit_group;" ::: "memory")
#define CP_WAIT1()  asm volatile("cp.async.wait_group 1;" ::: "memory")

__device__ __forceinline__ void ldm4(uint32_t* r, uint32_t addr) {
    asm volatile("ldmatrix.sync.aligned.m8n8.x4.shared.b16 {%0,%1,%2,%3}, [%4];"
        : "=r"(r[0]), "=r"(r[1]), "=r"(r[2]), "=r"(r[3]) : "r"(addr));
}
__device__ __forceinline__ void ldm4t(uint32_t* r, uint32_t addr) {
    asm volatile("ldmatrix.sync.aligned.m8n8.x4.trans.shared.b16 {%0,%1,%2,%3}, [%4];"
        : "=r"(r[0]), "=r"(r[1]), "=r"(r[2]), "=r"(r[3]) : "r"(addr));
}
__device__ __forceinline__ void mma_f16(float* d, const uint32_t* a,
                                        uint32_t b0, uint32_t b1) {
    asm volatile("mma.sync.aligned.m16n8k16.row.col.f32.f16.f16.f32 "
        "{%0,%1,%2,%3}, {%4,%5,%6,%7}, {%8,%9}, {%0,%1,%2,%3};"
        : "+f"(d[0]), "+f"(d[1]), "+f"(d[2]), "+f"(d[3])
        : "r"(a[0]), "r"(a[1]), "r"(a[2]), "r"(a[3]), "r"(b0), "r"(b1));
}

__device__ __forceinline__ void store_one_h(__half* hp, size_t idx, float x, float y) {
    *(__half2*)(hp + idx) = __halves2half2(__float2half_rn(x), __float2half_rn(y));
}

// ---------------- fused prep: X cvt | W cvt | Wo cvt | rope table ----------
__global__ void prep(const float* __restrict__ X,  const float* __restrict__ Wq,
                     const float* __restrict__ Wk, const float* __restrict__ Wv,
                     const float* __restrict__ Wo)
{
    int b = blockIdx.x, tid = threadIdx.x;
    if (b < 4096) {
        int i = b * 256 + tid;
        float4 v = ((const float4*)X)[i];
        ((__half2*)g_Xh)[2*i]   = __halves2half2(__float2half_rn(v.x), __float2half_rn(v.y));
        ((__half2*)g_Xh)[2*i+1] = __halves2half2(__float2half_rn(v.z), __float2half_rn(v.w));
    } else if (b < 4864) {
        int idx = (b - 4096) * 256 + tid;
        int y = idx >> 16;                    // 65536 float4 per matrix
        int i = idx & 65535;
        const float* s = (y == 0) ? Wq : (y == 1) ? Wk : Wv;
        __half* hp = g_Wh + (size_t)y * HIDN * HIDN;
        float4 v = ((const float4*)s)[i];
        ((__half2*)hp)[2*i]   = __halves2half2(__float2half_rn(v.x), __float2half_rn(v.y));
        ((__half2*)hp)[2*i+1] = __halves2half2(__float2half_rn(v.z), __float2half_rn(v.w));
    } else if (b < 5120) {
        int i = (b - 4864) * 256 + tid;
        float4 v = ((const float4*)Wo)[i];
        ((__half2*)g_Woh)[2*i]   = __halves2half2(__float2half_rn(v.x), __float2half_rn(v.y));
        ((__half2*)g_Woh)[2*i+1] = __halves2half2(__float2half_rn(v.z), __float2half_rn(v.w));
    } else {
        int j = (b - 5120) * 256 + tid;       // 65536 = 2048 pos x 32 freq
        int pos = j >> 5, f = j & 31;
        double li = 9.210340371976184 / 32.0; // ln(10000)/32
        float invf = (float)exp(-(double)f * li);
        float sn, cs;
        sincosf((float)pos * invf, &sn, &cs);
        g_rope[pos * 32 + f] = make_float2(cs, sn);
    }
}

// ---------------- mma.sync GEMM, fp16 1-pass (unchanged from R14) ----------
#define GROW    144
#define GTILE_B (128*GROW)            // 18432
#define GSTAGE_B (2*GTILE_B)          // A | B = 36864
#define GSMEM_BYTES (3*GSTAGE_B)      // 110592, 2 CTAs/SM

__global__ __launch_bounds__(256, 2) void gemm_mma(float* __restrict__ outp, int mode)
{
    extern __shared__ char smem[];
    uint32_t sb = smem_u32(smem);
    int tid = threadIdx.x, lane = tid & 31, warp = tid >> 5;
    int mw = warp & 3, nw = warp >> 2;
    int m0 = blockIdx.x * 128;
    int y  = blockIdx.y;
    int n0g = y * 128;

    const __half *Agh = (mode == 0) ? g_Xh : g_Ah;
    const __half *Bgh = (mode == 0) ? g_Wh : g_Woh;

    int lrow = tid >> 3, lc = tid & 7;               // 32 rows x 8 cols of 16B
    const __half* pA = Agh + (size_t)(m0 + lrow) * HIDN + lc * 8;
    const __half* pB = Bgh + (size_t)(n0g + lrow) * HIDN + lc * 8;
    uint32_t sdst = sb + lrow * GROW + lc * 16;

#define LDST(stb, c) do {                                                      \
    int _k = (c) * 64;                                                         \
    uint32_t _d = sdst + (stb);                                                \
    _Pragma("unroll")                                                          \
    for (int _p = 0; _p < 4; _p++) {                                           \
        uint32_t _o = _d + _p * (32 * GROW);                                   \
        size_t _g = _k + (size_t)_p * 32 * HIDN;                               \
        cp16(_o,           pA + _g);                                           \
        cp16(_o + GTILE_B, pB + _g);                                           \
    }                                                                          \
} while (0)

    float acc[2][8][4];
    #pragma unroll
    for (int a = 0; a < 2; a++)
        #pragma unroll
        for (int bq = 0; bq < 8; bq++)
            #pragma unroll
            for (int c = 0; c < 4; c++) acc[a][bq][c] = 0.f;

    uint32_t aaddr0 = sb + (mw * 32 + (lane & 15)) * GROW + (lane >> 4) * 16;
    uint32_t baddr0 = sb + GTILE_B + (nw * 64 + (lane & 15)) * GROW + (lane >> 4) * 16;

    LDST(0, 0);         CP_COMMIT();
    LDST(GSTAGE_B, 1);  CP_COMMIT();

    int cst = 0;
    int lst = 2 * GSTAGE_B;
    for (int c = 0; c < 8; c++) {
        CP_WAIT1();
        __syncthreads();
        if (c + 2 < 8) LDST(lst, c + 2);
        CP_COMMIT();
        uint32_t sa  = aaddr0 + cst;
        uint32_t sbb = baddr0 + cst;
        #pragma unroll
        for (int ks = 0; ks < 4; ks++) {
            uint32_t ka = sa + ks * 32, kb = sbb + ks * 32;
            uint32_t ah[2][4];
            ldm4(ah[0], ka);
            ldm4(ah[1], ka + 16*GROW);
            #pragma unroll
            for (int j = 0; j < 4; j++) {
                uint32_t bh[4];
                ldm4(bh, kb + j * (16*GROW));
                #pragma unroll
                for (int mi = 0; mi < 2; mi++) {
                    mma_f16(acc[mi][2*j],   ah[mi], bh[0], bh[2]);
                    mma_f16(acc[mi][2*j+1], ah[mi], bh[1], bh[3]);
                }
            }
        }
        cst = (cst == 2 * GSTAGE_B) ? 0 : cst + GSTAGE_B;
        lst = (lst == 2 * GSTAGE_B) ? 0 : lst + GSTAGE_B;
    }

    if (mode == 0) {
        int mat = y >> 2;                       // 0=Q,1=K,2=V
        int h   = ((y & 3) << 1) + nw;          // head
        __half* hp = (mat == 0) ? g_Qh : (mat == 1) ? g_Kh : g_Vh;
        #pragma unroll
        for (int mi = 0; mi < 2; mi++)
            #pragma unroll
            for (int half = 0; half < 2; half++) {
                int m = m0 + mw * 32 + mi * 16 + (lane >> 2) + half * 8;
                int bb = m >> 11, spos = m & (SEQ - 1);
                size_t base = ((size_t)(bb * NH + h) * SEQ + spos) * HD;
                int dlo = 2 * (lane & 3);
                if (mat == 2) {
                    #pragma unroll
                    for (int p = 0; p < 8; p++)
                        store_one_h(hp, base + p * 8 + dlo,
                                    acc[mi][p][2*half], acc[mi][p][2*half+1]);
                } else {
                    #pragma unroll
                    for (int p = 0; p < 4; p++) {
                        int d = p * 8 + dlo;
                        float4 t = *(const float4*)&g_rope[spos * 32 + d];
                        float a0 = acc[mi][p][2*half],   a1 = acc[mi][p][2*half+1];
                        float b0 = acc[mi][p+4][2*half], b1 = acc[mi][p+4][2*half+1];
                        store_one_h(hp, base + d,      a0*t.x - b0*t.y, a1*t.z - b1*t.w);
                        store_one_h(hp, base + d + 32, b0*t.x + a0*t.y, b1*t.z + a1*t.w);
                    }
                }
            }
    } else {
        #pragma unroll
        for (int mi = 0; mi < 2; mi++)
            #pragma unroll
            for (int half = 0; half < 2; half++) {
                int m = m0 + mw * 32 + mi * 16 + (lane >> 2) + half * 8;
                float* dst = outp + (size_t)m * HIDN + n0g + nw * 64 + 2 * (lane & 3);
                #pragma unroll
                for (int p = 0; p < 8; p++)
                    *(float2*)&dst[p * 8] =
                        make_float2(acc[mi][p][2*half], acc[mi][p][2*half+1]);
            }
    }
}

// ---------------- flash attention, fp16 1-pass ------------------------------
// Block = 128 q rows, 8 warps (16 rows each), k-tile 64, 3-stage cp.async.
// Per-warp whole-tile early-out (bit-exact) makes the wider block free of
// masked-tile MMA; K/V traffic and Q prologues halve vs 64-row blocks.
#define AST     144
#define QT_B    (128*AST)                       // 18432 (Q tile)
#define KT_B    (64*AST)                        // 9216 per K/V tile
#define ATTN_SMEM (QT_B + 3*2*KT_B)             // 73728, 2 CTAs/SM

__global__ __launch_bounds__(256) void attn_mma()
{
    extern __shared__ char smem[];
    uint32_t sb = smem_u32(smem);
    int tid = threadIdx.x, lane = tid & 31, warp = tid >> 5;
    int qt = blockIdx.x, h = blockIdx.y, b = blockIdx.z;
    int q0 = qt * 128;
    size_t hoff = (size_t)(b * NH + h) * SEQ * HD;
    const __half *Qhg = g_Qh + hoff + (size_t)q0 * HD;
    const __half *Khg = g_Kh + hoff;
    const __half *Vhg = g_Vh + hoff;

    // prologue: Q tile (128 rows x 8 c16 = 1024 cp16, 4/thread)
    #pragma unroll
    for (int p = 0; p < 4; p++) {
        int i = tid + p * 256;
        int row = i >> 3, c = i & 7;
        cp16(sb + (uint32_t)(row * AST + c * 16), Qhg + row * HD + c * 8);
    }

#define LOADKV(st, kb) do {                                                    \
    uint32_t _bs = sb + QT_B + (st) * 2*KT_B;                                  \
    _Pragma("unroll")                                                          \
    for (int p = 0; p < 2; p++) {                                              \
        int i = tid + p * 256;                                                 \
        int row = i >> 3, c = i & 7;                                           \
        uint32_t off = (uint32_t)(row * AST + c * 16);                         \
        const int so = ((kb) + row) * HD + c * 8;                              \
        cp16(_bs + off,        Khg + so);                                      \
        cp16(_bs + KT_B + off, Vhg + so);                                      \
    }                                                                          \
} while (0)

    int kt0 = (q0 > SWIN) ? ((q0 - SWIN) >> 6) : 0;
    int ktE = 2 * qt + 1;               // last tile covering q0+127
    LOADKV(0, kt0 * 64);
    CP_COMMIT();
    if (kt0 + 1 <= ktE) LOADKV(1, (kt0 + 1) * 64);
    CP_COMMIT();

    uint32_t qh[4][4];                  // A frags, 4 k16 chunks
    float O[8][4];
    #pragma unroll
    for (int j = 0; j < 8; j++)
        #pragma unroll
        for (int e = 0; e < 4; e++) O[j][e] = 0.f;
    float m0 = -1e30f, m1 = -1e30f, l0 = 0.f, l1 = 0.f;

    int rw  = q0 + warp * 16;           // warp's first q row
    int r0g = rw + (lane >> 2);
    int r1g = r0g + 8;

    for (int kt = kt0; kt <= ktE; kt++) {
        int i3 = kt - kt0;
        int st = i3 % 3;
        CP_WAIT1();
        __syncthreads();
        if (kt + 2 <= ktE) LOADKV((i3 + 2) % 3, (kt + 2) * 64);
        CP_COMMIT();

        if (kt == kt0) {
            uint32_t qa = sb + (warp * 16 + (lane & 15)) * AST + (lane >> 4) * 16;
            #pragma unroll
            for (int kc = 0; kc < 4; kc++)
                ldm4(qh[kc], qa + kc * 32);
        }

        int kb = kt * 64;
        // warp-level early-out: exactly (O*=1, l unchanged, m unchanged)
        if (kb > rw + 15 || kb + 63 < rw - SWIN) continue;

        uint32_t bs = sb + QT_B + st * 2*KT_B;

        // ---- raw scores = Q.K  (skip fully-masked 16-key groups)
        float sf[8][4];
        #pragma unroll
        for (int j = 0; j < 8; j++)
            #pragma unroll
            for (int e = 0; e < 4; e++) sf[j][e] = 0.f;

        uint32_t kaH = bs + (lane & 15) * AST + (lane >> 4) * 16;
        #pragma unroll
        for (int g = 0; g < 4; g++) {
            int kg = kb + 16 * g;
            if (kg > rw + 15 || kg + 15 < rw - SWIN) continue;   // exact: all masked
            #pragma unroll
            for (int kc = 0; kc < 4; kc++) {
                uint32_t bh[4];
                ldm4(bh, kaH + g * (16*AST) + kc * 32);
                mma_f16(sf[2*g],   qh[kc], bh[0], bh[2]);
                mma_f16(sf[2*g+1], qh[kc], bh[1], bh[3]);
            }
        }

        // ---- mask + 1/8 scale + online softmax (rows r0g, r1g)
        int c0 = kb + 2 * (lane & 3);
        float mx0 = -1e30f, mx1 = -1e30f;
        #pragma unroll
        for (int j = 0; j < 8; j++) {
            int k = c0 + 8 * j;
            sf[j][0] = ((unsigned)(r0g - k)     <= SWIN) ? sf[j][0] * 0.125f : -1e30f;
            sf[j][1] = ((unsigned)(r0g - k - 1) <= SWIN) ? sf[j][1] * 0.125f : -1e30f;
            sf[j][2] = ((unsigned)(r1g - k)     <= SWIN) ? sf[j][2] * 0.125f : -1e30f;
            sf[j][3] = ((unsigned)(r1g - k - 1) <= SWIN) ? sf[j][3] * 0.125f : -1e30f;
            mx0 = fmaxf(mx0, fmaxf(sf[j][0], sf[j][1]));
            mx1 = fmaxf(mx1, fmaxf(sf[j][2], sf[j][3]));
        }
        #pragma unroll
        for (int off = 1; off <= 2; off <<= 1) {
            mx0 = fmaxf(mx0, __shfl_xor_sync(0xffffffffu, mx0, off));
            mx1 = fmaxf(mx1, __shfl_xor_sync(0xffffffffu, mx1, off));
        }
        float mn0 = fmaxf(m0, mx0), mn1 = fmaxf(m1, mx1);
        float a0 = __expf(m0 - mn0), a1 = __expf(m1 - mn1);
        m0 = mn0; m1 = mn1;
        float s0 = 0.f, s1 = 0.f;
        #pragma unroll
        for (int j = 0; j < 8; j++) {
            sf[j][0] = __expf(sf[j][0] - mn0);
            sf[j][1] = __expf(sf[j][1] - mn0);
            sf[j][2] = __expf(sf[j][2] - mn1);
            sf[j][3] = __expf(sf[j][3] - mn1);
            s0 += sf[j][0] + sf[j][1];
            s1 += sf[j][2] + sf[j][3];
        }
        #pragma unroll
        for (int off = 1; off <= 2; off <<= 1) {
            s0 += __shfl_xor_sync(0xffffffffu, s0, off);
            s1 += __shfl_xor_sync(0xffffffffu, s1, off);
        }
        l0 = l0 * a0 + s0;
        l1 = l1 * a1 + s1;
        #pragma unroll
        for (int j = 0; j < 8; j++) {
            O[j][0] *= a0; O[j][1] *= a0; O[j][2] *= a1; O[j][3] *= a1;
        }

        // ---- O += P.V  (skip key groups with P exactly 0)
        uint32_t vaH = bs + KT_B + (lane & 15) * AST + (lane >> 4) * 16;
        #pragma unroll
        for (int kc = 0; kc < 4; kc++) {
            int kg = kb + 16 * kc;
            if (kg > rw + 15 || kg + 15 < rw - SWIN) continue;   // P == 0 here
            uint32_t pah[4];
            #pragma unroll
            for (int half = 0; half < 2; half++) {
                int j = 2 * kc + half;
                #pragma unroll
                for (int rr = 0; rr < 2; rr++) {
                    __half2 hh = __halves2half2(__float2half_rn(sf[j][2*rr]),
                                                __float2half_rn(sf[j][2*rr + 1]));
                    pah[2*half + rr] = *(uint32_t*)&hh;
                }
            }
            #pragma unroll
            for (int dj = 0; dj < 4; dj++) {
                uint32_t vh[4];
                ldm4t(vh, vaH + kc * (16*AST) + dj * 32);
                mma_f16(O[2*dj],   pah, vh[0], vh[1]);
                mma_f16(O[2*dj+1], pah, vh[2], vh[3]);
            }
        }
    }

    // ---- epilogue: write fp16 A (single-rounded; out-proj is 1-pass)
    float il0 = 1.0f / l0, il1 = 1.0f / l1;
    int dlo = 2 * (lane & 3);
    size_t base0 = ((size_t)(b * SEQ + r0g)) * HIDN + h * HD + dlo;
    size_t base1 = ((size_t)(b * SEQ + r1g)) * HIDN + h * HD + dlo;
    #pragma unroll
    for (int j = 0; j < 8; j++) {
        store_one_h(g_Ah, base0 + 8*j, O[j][0] * il0, O[j][1] * il0);
        store_one_h(g_Ah, base1 + 8*j, O[j][2] * il1, O[j][3] * il1);
    }
}

// ---------------- launch ---------------------------------------------------
extern "C" void kernel_launch(void* const* d_in, const int* in_sizes, int n_in,
                              void* d_out, int out_size)
{
    const float* X  = (const float*)d_in[0];
    const float* Wq = (const float*)d_in[2];
    const float* Wk = (const float*)d_in[3];
    const float* Wv = (const float*)d_in[4];
    const float* Wo = (const float*)d_in[5];
    float* out = (float*)d_out;

    cudaFuncSetAttribute(gemm_mma, cudaFuncAttributeMaxDynamicSharedMemorySize,
                         GSMEM_BYTES);
    cudaFuncSetAttribute(attn_mma, cudaFuncAttributeMaxDynamicSharedMemorySize,
                         ATTN_SMEM);

    prep<<<5376, 256>>>(X, Wq, Wk, Wv, Wo);                               // 0
    gemm_mma<<<dim3(MTOT / 128, 12), 256, GSMEM_BYTES>>>(nullptr, 0);     // 1
    attn_mma<<<dim3(SEQ / 128, NH, BATCH), 256, ATTN_SMEM>>>();           // 2
    gemm_mma<<<dim3(MTOT / 128, HIDN / 128), 256, GSMEM_BYTES>>>(out, 1); // 3
}

// round 16
// speedup vs baseline: 1.0178x; 1.0178x over previous
#include <cuda_runtime.h>
#include <cuda_fp16.h>
#include <math.h>
#include <stdint.h>

#define BATCH 4
#define SEQ   2048
#define HIDN  512
#define NH    8
#define HD    64
#define SWIN  250
#define MTOT  (BATCH*SEQ)            // 8192
#define MATSZ (BATCH*NH*SEQ*HD)      // 4.19M elements per Q/K/V matrix

// scale folded with log2(e): scores enter softmax in log2 domain
#define SCL2E 0.18033688011112042f   // 0.125 * log2(e)

// ---------------- device-global scratch (fp16, all single-rounded) ----------
__device__ __half g_Xh[MTOT*HIDN];                    // X rounded once
__device__ __half g_Wh[3*HIDN*HIDN];                  // Wq|Wk|Wv rounded once
__device__ __half g_Ah[MTOT*HIDN];                    // attn out, rounded once
__device__ __half g_Woh[HIDN*HIDN];                   // Wo rounded once
__device__ __half g_Qh[MATSZ];                        // RoPE'd Q (UNscaled)
__device__ __half g_Kh[MATSZ];                        // RoPE'd K
__device__ __half g_Vh[MATSZ];                        // V
__device__ float2 g_rope[SEQ*32];                     // cos,sin per (pos, freq)

// ---------------- PTX helpers ----------------------------------------------
__device__ __forceinline__ uint32_t smem_u32(const void* p) {
    uint32_t a;
    asm("{ .reg .u64 t; cvta.to.shared.u64 t, %1; cvt.u32.u64 %0, t; }"
        : "=r"(a) : "l"(p));
    return a;
}
__device__ __forceinline__ void cp16(uint32_t d, const void* s) {
    asm volatile("cp.async.cg.shared.global [%0], [%1], 16;"
                 :: "r"(d), "l"(__cvta_generic_to_global(s)) : "memory");
}
#define CP_COMMIT() asm volatile("cp.async.commit_group;" ::: "memory")
#define CP_WAIT1()  asm volatile("cp.async.wait_group 1;" ::: "memory")

__device__ __forceinline__ void ldm4(uint32_t* r, uint32_t addr) {
    asm volatile("ldmatrix.sync.aligned.m8n8.x4.shared.b16 {%0,%1,%2,%3}, [%4];"
        : "=r"(r[0]), "=r"(r[1]), "=r"(r[2]), "=r"(r[3]) : "r"(addr));
}
__device__ __forceinline__ void ldm4t(uint32_t* r, uint32_t addr) {
    asm volatile("ldmatrix.sync.aligned.m8n8.x4.trans.shared.b16 {%0,%1,%2,%3}, [%4];"
        : "=r"(r[0]), "=r"(r[1]), "=r"(r[2]), "=r"(r[3]) : "r"(addr));
}
__device__ __forceinline__ void mma_f16(float* d, const uint32_t* a,
                                        uint32_t b0, uint32_t b1) {
    asm volatile("mma.sync.aligned.m16n8k16.row.col.f32.f16.f16.f32 "
        "{%0,%1,%2,%3}, {%4,%5,%6,%7}, {%8,%9}, {%0,%1,%2,%3};"
        : "+f"(d[0]), "+f"(d[1]), "+f"(d[2]), "+f"(d[3])
        : "r"(a[0]), "r"(a[1]), "r"(a[2]), "r"(a[3]), "r"(b0), "r"(b1));
}

__device__ __forceinline__ void store_one_h(__half* hp, size_t idx, float x, float y) {
    *(__half2*)(hp + idx) = __float22half2_rn(make_float2(x, y));
}

// ---------------- fused prep: X cvt | W cvt | Wo cvt | rope table ----------
__global__ void prep(const float* __restrict__ X,  const float* __restrict__ Wq,
                     const float* __restrict__ Wk, const float* __restrict__ Wv,
                     const float* __restrict__ Wo)
{
    int b = blockIdx.x, tid = threadIdx.x;
    if (b < 4096) {
        int i = b * 256 + tid;
        float4 v = ((const float4*)X)[i];
        ((__half2*)g_Xh)[2*i]   = __float22half2_rn(make_float2(v.x, v.y));
        ((__half2*)g_Xh)[2*i+1] = __float22half2_rn(make_float2(v.z, v.w));
    } else if (b < 4864) {
        int idx = (b - 4096) * 256 + tid;
        int y = idx >> 16;                    // 65536 float4 per matrix
        int i = idx & 65535;
        const float* s = (y == 0) ? Wq : (y == 1) ? Wk : Wv;
        __half* hp = g_Wh + (size_t)y * HIDN * HIDN;
        float4 v = ((const float4*)s)[i];
        ((__half2*)hp)[2*i]   = __float22half2_rn(make_float2(v.x, v.y));
        ((__half2*)hp)[2*i+1] = __float22half2_rn(make_float2(v.z, v.w));
    } else if (b < 5120) {
        int i = (b - 4864) * 256 + tid;
        float4 v = ((const float4*)Wo)[i];
        ((__half2*)g_Woh)[2*i]   = __float22half2_rn(make_float2(v.x, v.y));
        ((__half2*)g_Woh)[2*i+1] = __float22half2_rn(make_float2(v.z, v.w));
    } else {
        int j = (b - 5120) * 256 + tid;       // 65536 = 2048 pos x 32 freq
        int pos = j >> 5, f = j & 31;
        double li = 9.210340371976184 / 32.0; // ln(10000)/32
        float invf = (float)exp(-(double)f * li);
        float sn, cs;
        sincosf((float)pos * invf, &sn, &cs);
        g_rope[pos * 32 + f] = make_float2(cs, sn);
    }
}

// ---------------- mma.sync GEMM, fp16 1-pass (R14 config) ------------------
#define GROW    144
#define GTILE_B (128*GROW)            // 18432
#define GSTAGE_B (2*GTILE_B)          // A | B = 36864
#define GSMEM_BYTES (3*GSTAGE_B)      // 110592, 2 CTAs/SM

__global__ __launch_bounds__(256, 2) void gemm_mma(float* __restrict__ outp, int mode)
{
    extern __shared__ char smem[];
    uint32_t sb = smem_u32(smem);
    int tid = threadIdx.x, lane = tid & 31, warp = tid >> 5;
    int mw = warp & 3, nw = warp >> 2;
    int m0 = blockIdx.x * 128;
    int y  = blockIdx.y;
    int n0g = y * 128;

    const __half *Agh = (mode == 0) ? g_Xh : g_Ah;
    const __half *Bgh = (mode == 0) ? g_Wh : g_Woh;

    int lrow = tid >> 3, lc = tid & 7;               // 32 rows x 8 cols of 16B
    const __half* pA = Agh + (size_t)(m0 + lrow) * HIDN + lc * 8;
    const __half* pB = Bgh + (size_t)(n0g + lrow) * HIDN + lc * 8;
    uint32_t sdst = sb + lrow * GROW + lc * 16;

#define LDST(stb, c) do {                                                      \
    int _k = (c) * 64;                                                         \
    uint32_t _d = sdst + (stb);                                                \
    _Pragma("unroll")                                                          \
    for (int _p = 0; _p < 4; _p++) {                                           \
        uint32_t _o = _d + _p * (32 * GROW);                                   \
        size_t _g = _k + (size_t)_p * 32 * HIDN;                               \
        cp16(_o,           pA + _g);                                           \
        cp16(_o + GTILE_B, pB + _g);                                           \
    }                                                                          \
} while (0)

    float acc[2][8][4];
    #pragma unroll
    for (int a = 0; a < 2; a++)
        #pragma unroll
        for (int bq = 0; bq < 8; bq++)
            #pragma unroll
            for (int c = 0; c < 4; c++) acc[a][bq][c] = 0.f;

    uint32_t aaddr0 = sb + (mw * 32 + (lane & 15)) * GROW + (lane >> 4) * 16;
    uint32_t baddr0 = sb + GTILE_B + (nw * 64 + (lane & 15)) * GROW + (lane >> 4) * 16;

    LDST(0, 0);         CP_COMMIT();
    LDST(GSTAGE_B, 1);  CP_COMMIT();

    int cst = 0;
    int lst = 2 * GSTAGE_B;
    for (int c = 0; c < 8; c++) {
        CP_WAIT1();
        __syncthreads();
        if (c + 2 < 8) LDST(lst, c + 2);
        CP_COMMIT();
        uint32_t sa  = aaddr0 + cst;
        uint32_t sbb = baddr0 + cst;
        #pragma unroll
        for (int ks = 0; ks < 4; ks++) {
            uint32_t ka = sa + ks * 32, kb = sbb + ks * 32;
            uint32_t ah[2][4];
            ldm4(ah[0], ka);
            ldm4(ah[1], ka + 16*GROW);
            #pragma unroll
            for (int j = 0; j < 4; j++) {
                uint32_t bh[4];
                ldm4(bh, kb + j * (16*GROW));
                #pragma unroll
                for (int mi = 0; mi < 2; mi++) {
                    mma_f16(acc[mi][2*j],   ah[mi], bh[0], bh[2]);
                    mma_f16(acc[mi][2*j+1], ah[mi], bh[1], bh[3]);
                }
            }
        }
        cst = (cst == 2 * GSTAGE_B) ? 0 : cst + GSTAGE_B;
        lst = (lst == 2 * GSTAGE_B) ? 0 : lst + GSTAGE_B;
    }

    if (mode == 0) {
        int mat = y >> 2;                       // 0=Q,1=K,2=V
        int h   = ((y & 3) << 1) + nw;          // head
        __half* hp = (mat == 0) ? g_Qh : (mat == 1) ? g_Kh : g_Vh;
        #pragma unroll
        for (int mi = 0; mi < 2; mi++)
            #pragma unroll
            for (int half = 0; half < 2; half++) {
                int m = m0 + mw * 32 + mi * 16 + (lane >> 2) + half * 8;
                int bb = m >> 11, spos = m & (SEQ - 1);
                size_t base = ((size_t)(bb * NH + h) * SEQ + spos) * HD;
                int dlo = 2 * (lane & 3);
                if (mat == 2) {
                    #pragma unroll
                    for (int p = 0; p < 8; p++)
                        store_one_h(hp, base + p * 8 + dlo,
                                    acc[mi][p][2*half], acc[mi][p][2*half+1]);
                } else {
                    #pragma unroll
                    for (int p = 0; p < 4; p++) {
                        int d = p * 8 + dlo;
                        float4 t = *(const float4*)&g_rope[spos * 32 + d];
                        float a0 = acc[mi][p][2*half],   a1 = acc[mi][p][2*half+1];
                        float b0 = acc[mi][p+4][2*half], b1 = acc[mi][p+4][2*half+1];
                        store_one_h(hp, base + d,      a0*t.x - b0*t.y, a1*t.z - b1*t.w);
                        store_one_h(hp, base + d + 32, b0*t.x + a0*t.y, b1*t.z + a1*t.w);
                    }
                }
            }
    } else {
        #pragma unroll
        for (int mi = 0; mi < 2; mi++)
            #pragma unroll
            for (int half = 0; half < 2; half++) {
                int m = m0 + mw * 32 + mi * 16 + (lane >> 2) + half * 8;
                float* dst = outp + (size_t)m * HIDN + n0g + nw * 64 + 2 * (lane & 3);
                #pragma unroll
                for (int p = 0; p < 8; p++)
                    *(float2*)&dst[p * 8] =
                        make_float2(acc[mi][p][2*half], acc[mi][p][2*half+1]);
            }
    }
}

// ---------------- flash attention, fp16 1-pass ------------------------------
// Block = 64 q rows, 4 warps, k-tile 64, 3-stage cp.async, ONE barrier/iter.
// Base-2 softmax (scale pre-folded with log2e). Warp-level whole-tile
// early-out (bit-exact) + 16-key group skipping.
#define AST     144
#define KT_B    (64*AST)                        // 9216 per tile
#define ATTN_SMEM (KT_B + 3*2*KT_B)             // Qh + 3 stages x (Kh,Vh) = 64512

__global__ __launch_bounds__(128) void attn_mma()
{
    extern __shared__ char smem[];
    uint32_t sb = smem_u32(smem);
    int tid = threadIdx.x, lane = tid & 31, warp = tid >> 5;
    int qt = blockIdx.x, h = blockIdx.y, b = blockIdx.z;
    int q0 = qt * 64;
    size_t hoff = (size_t)(b * NH + h) * SEQ * HD;
    const __half *Qhg = g_Qh + hoff + (size_t)q0 * HD;
    const __half *Khg = g_Kh + hoff;
    const __half *Vhg = g_Vh + hoff;

    // prologue: Q tile (folded into stage-0 commit group)
    #pragma unroll
    for (int p = 0; p < 4; p++) {
        int i = tid + p * 128;
        int row = i >> 3, c = i & 7;
        if (row < 64)
            cp16(sb + (uint32_t)(row * AST + c * 16), Qhg + row * HD + c * 8);
    }

#define LOADKV(st, kb) do {                                                    \
    uint32_t _bs = sb + KT_B + (st) * 2*KT_B;                                  \
    _Pragma("unroll")                                                          \
    for (int p = 0; p < 4; p++) {                                              \
        int i = tid + p * 128;                                                 \
        int row = i >> 3, c = i & 7;                                           \
        uint32_t off = (uint32_t)(row * AST + c * 16);                         \
        const int so = ((kb) + row) * HD + c * 8;                              \
        cp16(_bs + off,        Khg + so);                                      \
        cp16(_bs + KT_B + off, Vhg + so);                                      \
    }                                                                          \
} while (0)

    int kt0 = (q0 > SWIN) ? ((q0 - SWIN) >> 6) : 0;
    LOADKV(0, kt0 * 64);
    CP_COMMIT();
    if (kt0 + 1 <= qt) LOADKV(1, (kt0 + 1) * 64);
    CP_COMMIT();

    uint32_t qh[4][4];                  // A frags, 4 k16 chunks
    float O[8][4];
    #pragma unroll
    for (int j = 0; j < 8; j++)
        #pragma unroll
        for (int e = 0; e < 4; e++) O[j][e] = 0.f;
    float m0 = -1e30f, m1 = -1e30f, l0 = 0.f, l1 = 0.f;

    int rw  = q0 + warp * 16;           // warp's first q row
    int r0g = rw + (lane >> 2);
    int r1g = r0g + 8;

    for (int kt = kt0; kt <= qt; kt++) {
        int i3 = kt - kt0;
        int st = i3 % 3;
        CP_WAIT1();
        __syncthreads();
        if (kt + 2 <= qt) LOADKV((i3 + 2) % 3, (kt + 2) * 64);
        CP_COMMIT();

        if (kt == kt0) {
            uint32_t qa = sb + (warp * 16 + (lane & 15)) * AST + (lane >> 4) * 16;
            #pragma unroll
            for (int kc = 0; kc < 4; kc++)
                ldm4(qh[kc], qa + kc * 32);
        }

        int kb = kt * 64;
        // warp-level early-out: exactly (O*=1, l unchanged, m unchanged)
        if (kb > rw + 15 || kb + 63 < rw - SWIN) continue;

        uint32_t bs = sb + KT_B + st * 2*KT_B;

        // ---- raw scores = Q.K  (skip fully-masked 16-key groups)
        float sf[8][4];
        #pragma unroll
        for (int j = 0; j < 8; j++)
            #pragma unroll
            for (int e = 0; e < 4; e++) sf[j][e] = 0.f;

        uint32_t kaH = bs + (lane & 15) * AST + (lane >> 4) * 16;
        #pragma unroll
        for (int g = 0; g < 4; g++) {
            int kg = kb + 16 * g;
            if (kg > rw + 15 || kg + 15 < rw - SWIN) continue;   // exact: all masked
            #pragma unroll
            for (int kc = 0; kc < 4; kc++) {
                uint32_t bh[4];
                ldm4(bh, kaH + g * (16*AST) + kc * 32);
                mma_f16(sf[2*g],   qh[kc], bh[0], bh[2]);
                mma_f16(sf[2*g+1], qh[kc], bh[1], bh[3]);
            }
        }

        // ---- mask + log2-domain scale + online softmax (rows r0g, r1g)
        int c0 = kb + 2 * (lane & 3);
        float mx0 = -1e30f, mx1 = -1e30f;
        #pragma unroll
        for (int j = 0; j < 8; j++) {
            int k = c0 + 8 * j;
            sf[j][0] = ((unsigned)(r0g - k)     <= SWIN) ? sf[j][0] * SCL2E : -1e30f;
            sf[j][1] = ((unsigned)(r0g - k - 1) <= SWIN) ? sf[j][1] * SCL2E : -1e30f;
            sf[j][2] = ((unsigned)(r1g - k)     <= SWIN) ? sf[j][2] * SCL2E : -1e30f;
            sf[j][3] = ((unsigned)(r1g - k - 1) <= SWIN) ? sf[j][3] * SCL2E : -1e30f;
            mx0 = fmaxf(mx0, fmaxf(sf[j][0], sf[j][1]));
            mx1 = fmaxf(mx1, fmaxf(sf[j][2], sf[j][3]));
        }
        #pragma unroll
        for (int off = 1; off <= 2; off <<= 1) {
            mx0 = fmaxf(mx0, __shfl_xor_sync(0xffffffffu, mx0, off));
            mx1 = fmaxf(mx1, __shfl_xor_sync(0xffffffffu, mx1, off));
        }
        float mn0 = fmaxf(m0, mx0), mn1 = fmaxf(m1, mx1);
        float a0 = exp2f(m0 - mn0), a1 = exp2f(m1 - mn1);
        m0 = mn0; m1 = mn1;
        float s0 = 0.f, s1 = 0.f;
        #pragma unroll
        for (int j = 0; j < 8; j++) {
            sf[j][0] = exp2f(sf[j][0] - mn0);
            sf[j][1] = exp2f(sf[j][1] - mn0);
            sf[j][2] = exp2f(sf[j][2] - mn1);
            sf[j][3] = exp2f(sf[j][3] - mn1);
            s0 += sf[j][0] + sf[j][1];
            s1 += sf[j][2] + sf[j][3];
        }
        #pragma unroll
        for (int off = 1; off <= 2; off <<= 1) {
            s0 += __shfl_xor_sync(0xffffffffu, s0, off);
            s1 += __shfl_xor_sync(0xffffffffu, s1, off);
        }
        l0 = l0 * a0 + s0;
        l1 = l1 * a1 + s1;
        #pragma unroll
        for (int j = 0; j < 8; j++) {
            O[j][0] *= a0; O[j][1] *= a0; O[j][2] *= a1; O[j][3] *= a1;
        }

        // ---- O += P.V  (skip key groups with P exactly 0)
        uint32_t vaH = bs + KT_B + (lane & 15) * AST + (lane >> 4) * 16;
        #pragma unroll
        for (int kc = 0; kc < 4; kc++) {
            int kg = kb + 16 * kc;
            if (kg > rw + 15 || kg + 15 < rw - SWIN) continue;   // P == 0 here
            uint32_t pah[4];
            #pragma unroll
            for (int half = 0; half < 2; half++) {
                int j = 2 * kc + half;
                #pragma unroll
                for (int rr = 0; rr < 2; rr++) {
                    __half2 hh = __float22half2_rn(
                        make_float2(sf[j][2*rr], sf[j][2*rr + 1]));
                    pah[2*half + rr] = *(uint32_t*)&hh;
                }
            }
            #pragma unroll
            for (int dj = 0; dj < 4; dj++) {
                uint32_t vh[4];
                ldm4t(vh, vaH + kc * (16*AST) + dj * 32);
                mma_f16(O[2*dj],   pah, vh[0], vh[1]);
                mma_f16(O[2*dj+1], pah, vh[2], vh[3]);
            }
        }
    }

    // ---- epilogue: write fp16 A (single-rounded; out-proj is 1-pass)
    float il0 = 1.0f / l0, il1 = 1.0f / l1;
    int dlo = 2 * (lane & 3);
    size_t base0 = ((size_t)(b * SEQ + r0g)) * HIDN + h * HD + dlo;
    size_t base1 = ((size_t)(b * SEQ + r1g)) * HIDN + h * HD + dlo;
    #pragma unroll
    for (int j = 0; j < 8; j++) {
        store_one_h(g_Ah, base0 + 8*j, O[j][0] * il0, O[j][1] * il0);
        store_one_h(g_Ah, base1 + 8*j, O[j][2] * il1, O[j][3] * il1);
    }
}

// ---------------- launch ---------------------------------------------------
extern "C" void kernel_launch(void* const* d_in, const int* in_sizes, int n_in,
                              void* d_out, int out_size)
{
    const float* X  = (const float*)d_in[0];
    const float* Wq = (const float*)d_in[2];
    const float* Wk = (const float*)d_in[3];
    const float* Wv = (const float*)d_in[4];
    const float* Wo = (const float*)d_in[5];
    float* out = (float*)d_out;

    cudaFuncSetAttribute(gemm_mma, cudaFuncAttributeMaxDynamicSharedMemorySize,
                         GSMEM_BYTES);
    cudaFuncSetAttribute(attn_mma, cudaFuncAttributeMaxDynamicSharedMemorySize,
                         ATTN_SMEM);

    prep<<<5376, 256>>>(X, Wq, Wk, Wv, Wo);                               // 0
    gemm_mma<<<dim3(MTOT / 128, 12), 256, GSMEM_BYTES>>>(nullptr, 0);     // 1
    attn_mma<<<dim3(SEQ / 64, NH, BATCH), 128, ATTN_SMEM>>>();            // 2
    gemm_mma<<<dim3(MTOT / 128, HIDN / 128), 256, GSMEM_BYTES>>>(out, 1); // 3
}